// round 13
// baseline (speedup 1.0000x reference)
#include <cuda_runtime.h>
#include <math.h>

#define Cn 4096
#define Vn 32000
#define Hn 256
#define Dn 128
#define Nb 16
#define Tt 256
#define NBLK 128
#define NG 8   // batches per group

// ---------------- device scratch (static) ----------------
__device__ float g_Xn[Vn * Hn];        // normalized-row staging (max V rows)
__device__ float g_t1[Cn * Hn];
__device__ float g_f1[Cn * Hn];
__device__ float g_t2[Cn * Hn];
__device__ float g_ft[Cn * Hn];
__device__ float g_Eyn[Cn * Dn];       // features of next_state_emb
__device__ float g_Exn[Cn * Dn];       // features of state_emb (row-normalized: ExnN·Sn = 1)
__device__ float g_Ext[Cn * Dn];       // features of terminal-MLP out (row-normalized by Se)
__device__ float g_Ele[Vn * Dn];       // features of terminal_emb
__device__ float g_Sn[Dn];
__device__ float g_Se[Dn];
__device__ float g_Exs[Dn];
__device__ float g_buf2[2][3][NG * Dn]; // per-group rotating G-state buffers
__device__ float g_Zs[2][Tt][NG];       // z table: [g][0]=final z, [g][1..255]=in-loop z
__device__ unsigned g_bar2[2];
__device__ volatile unsigned g_gen2[2];

// ---------------- zero / reset ----------------
__global__ __launch_bounds__(128) void kzero() {
    int i = threadIdx.x;
    if (i < Dn) { g_Sn[i] = 0.f; g_Se[i] = 0.f; }
    if (i < 2) { g_bar2[i] = 0u; g_gen2[i] = 0u; }
}

// ------------- generic tiled GEMM: Out = epi(A[M,K]@W[K,N]) -------------
// mode 1: relu(+bias); 2: relu(+bias)+R; 3: exp(x-0.5)
__global__ __launch_bounds__(256) void kgemm(const float* __restrict__ A,
                                             const float* __restrict__ W,
                                             const float* __restrict__ bias,
                                             const float* __restrict__ R,
                                             float* __restrict__ Out,
                                             int M, int N, int K, int mode) {
    __shared__ float As[16][68];
    __shared__ float Ws[16][68];
    int tid = threadIdx.x;
    int m0 = blockIdx.x * 64, n0 = blockIdx.y * 64;
    int ar = tid >> 2, ak = (tid & 3) * 4;
    int wk = tid >> 4, wn = (tid & 15) * 4;
    int ty = tid >> 4, tx = tid & 15;
    float acc[4][4] = {};
    for (int kt = 0; kt < K; kt += 16) {
        float4 av = *(const float4*)(A + (size_t)(m0 + ar) * K + kt + ak);
        As[ak + 0][ar] = av.x; As[ak + 1][ar] = av.y;
        As[ak + 2][ar] = av.z; As[ak + 3][ar] = av.w;
        *(float4*)&Ws[wk][wn] = *(const float4*)(W + (size_t)(kt + wk) * N + n0 + wn);
        __syncthreads();
#pragma unroll
        for (int k = 0; k < 16; k++) {
            float a[4], b[4];
            *(float4*)a = *(const float4*)&As[k][ty * 4];
            *(float4*)b = *(const float4*)&Ws[k][tx * 4];
#pragma unroll
            for (int i = 0; i < 4; i++)
#pragma unroll
                for (int j = 0; j < 4; j++) acc[i][j] += a[i] * b[j];
        }
        __syncthreads();
    }
#pragma unroll
    for (int i = 0; i < 4; i++) {
        int m = m0 + ty * 4 + i;
#pragma unroll
        for (int j = 0; j < 4; j++) {
            int n = n0 + tx * 4 + j;
            float v = acc[i][j];
            if (mode == 1 || mode == 2) v = fmaxf(v + bias[n], 0.f);
            if (mode == 2) v += R[(size_t)m * N + n];
            if (mode == 3) v = expf(v - 0.5f);
            Out[(size_t)m * N + n] = v;
        }
    }
}

// ------------- row l2-normalize -------------
__global__ __launch_bounds__(256) void krownorm(const float* __restrict__ X,
                                                float* __restrict__ Xn) {
    int r = blockIdx.x, tid = threadIdx.x;
    __shared__ float red[8];
    float v = X[(size_t)r * Hn + tid];
    float ss = v * v;
#pragma unroll
    for (int o = 16; o; o >>= 1) ss += __shfl_xor_sync(~0u, ss, o);
    if ((tid & 31) == 0) red[tid >> 5] = ss;
    __syncthreads();
    float tot = 0.f;
#pragma unroll
    for (int i = 0; i < 8; i++) tot += red[i];
    Xn[(size_t)r * Hn + tid] = v * rsqrtf(tot);
}

// ------------- column sums -------------
__global__ __launch_bounds__(128) void kcolsum(const float* __restrict__ E, int rows,
                                               float* __restrict__ S) {
    int d = threadIdx.x;
    float acc = 0.f;
    for (int r = blockIdx.x; r < rows; r += gridDim.x) acc += E[(size_t)r * Dn + d];
    atomicAdd(&S[d], acc);
}

// ------------- row normalize: E[r,:] /= (E[r,:]·S) -------------
__global__ __launch_bounds__(128) void krowdiv(float* __restrict__ E,
                                               const float* __restrict__ S) {
    int r = blockIdx.x, tid = threadIdx.x;
    __shared__ float red[4];
    float v = E[(size_t)r * Dn + tid];
    float p = v * S[tid];
#pragma unroll
    for (int o = 16; o; o >>= 1) p += __shfl_xor_sync(~0u, p, o);
    if ((tid & 31) == 0) red[tid >> 5] = p;
    __syncthreads();
    float u = red[0] + red[1] + red[2] + red[3];
    E[(size_t)r * Dn + tid] = v / u;
}

// ------------- start MLP + features of the single start vector -------------
__global__ __launch_bounds__(256) void kstartmlp(
    const float* se, const float* w0, const float* b0,
    const float* w1, const float* b1, const float* w2, const float* b2,
    const float* w3, const float* b3, const float* w4, const float* b4,
    const float* proj) {
    __shared__ float xs[256], Ab[256], Bb[256], Cb[256];
    __shared__ float red[8], sinv;
    int tid = threadIdx.x;
    xs[tid] = se[tid];
    __syncthreads();
    float acc = 0.f;
    for (int i = 0; i < 256; i++) acc += xs[i] * w0[i * 256 + tid];
    Ab[tid] = acc + b0[tid];
    __syncthreads();
    acc = 0.f;
    for (int i = 0; i < 256; i++) acc += Ab[i] * w1[i * 256 + tid];
    Bb[tid] = fmaxf(acc + b1[tid], 0.f);
    __syncthreads();
    acc = 0.f;
    for (int i = 0; i < 256; i++) acc += Bb[i] * w2[i * 256 + tid];
    Cb[tid] = fmaxf(acc + b2[tid], 0.f) + Ab[tid];
    __syncthreads();
    acc = 0.f;
    for (int i = 0; i < 256; i++) acc += Cb[i] * w3[i * 256 + tid];
    __syncthreads();
    Bb[tid] = fmaxf(acc + b3[tid], 0.f);
    __syncthreads();
    acc = 0.f;
    for (int i = 0; i < 256; i++) acc += Bb[i] * w4[i * 256 + tid];
    Ab[tid] = fmaxf(acc + b4[tid], 0.f) + Cb[tid];
    __syncthreads();
    float ss = Ab[tid] * Ab[tid];
#pragma unroll
    for (int o = 16; o; o >>= 1) ss += __shfl_xor_sync(~0u, ss, o);
    if ((tid & 31) == 0) red[tid >> 5] = ss;
    __syncthreads();
    if (tid == 0) {
        float t = 0.f;
        for (int i = 0; i < 8; i++) t += red[i];
        sinv = rsqrtf(t);
    }
    __syncthreads();
    if (tid < 128) {
        float a2 = 0.f;
        for (int i = 0; i < 256; i++) a2 += Ab[i] * proj[i * 128 + tid];
        g_Exs[tid] = expf(a2 * sinv - 0.5f);
    }
}

// =========== persistent recursion: two interleaved 8-seq recursions ===========
#define GB_ARRIVE(g)                                                           \
    do {                                                                       \
        __threadfence();                                                       \
        __syncthreads();                                                       \
        if (tid == 0) {                                                        \
            if (atomicAdd(&g_bar2[g], 1u) == NBLK - 1u) {                      \
                atomicExch(&g_bar2[g], 0u);                                    \
                __threadfence();                                               \
                atomicAdd((unsigned*)&g_gen2[g], 1u);                          \
            }                                                                  \
        }                                                                      \
    } while (0)

#define GB_WAIT(g, gen)                                                        \
    do {                                                                       \
        if (tid == 0) {                                                        \
            while (g_gen2[g] <= (gen)) __nanosleep(32);                        \
        }                                                                      \
        __syncthreads();                                                       \
        (gen)++;                                                               \
    } while (0)

__global__ __launch_bounds__(256, 1) void krec(const int* __restrict__ text,
                                               float* __restrict__ out) {
    __shared__ float Gs[2][NG][132];    // 132-pad: conflict-free A-phase LDS
    __shared__ float Egs[2][NG][132];
    __shared__ float Ash[2][NG][32];
    __shared__ float snS[Dn];
    int tid = threadIdx.x;
    int blk = blockIdx.x;
    int w = tid >> 5, lane = tid & 31;
    int cl = tid >> 3, q = tid & 7;       // 32 states/block, 8 lanes/state
    int dd = tid & 127, half = tid >> 7;  // G'-phase indexing
    unsigned genA = 0, genB = 0;

    // persistent operands: thread owns dims {j*32 + q*4 .. +3} of its state row
    float a[16], b[16], xn[32];
    {
        const float4* ap = (const float4*)(g_Ext + (size_t)(blk * 32 + cl) * Dn + q * 4);
        const float4* bp = (const float4*)(g_Eyn + (size_t)(blk * 32 + cl) * Dn + q * 4);
#pragma unroll
        for (int j = 0; j < 4; j++) {
            *(float4*)&a[j * 4] = ap[j * 8];
            *(float4*)&b[j * 4] = bp[j * 8];
        }
#pragma unroll
        for (int c = 0; c < 32; c++) xn[c] = g_Exn[(size_t)(blk * 32 + c) * Dn + dd];
    }
    if (tid < Dn) snS[tid] = g_Sn[tid];

    // init both groups: buf0 = Exs replicated, buf1 = 0 (block-partitioned)
    if (tid < 8) {
        int o = blk * 8 + tid;
        int d = o & 127;
        __stcg(&g_buf2[0][0][o], g_Exs[d]);
        __stcg(&g_buf2[0][1][o], 0.f);
        __stcg(&g_buf2[1][0][o], g_Exs[d]);
        __stcg(&g_buf2[1][1][o], 0.f);
    }
    GB_ARRIVE(0);
    GB_ARRIVE(1);

    float* bA0 = g_buf2[0][0]; float* bA1 = g_buf2[0][1]; float* bA2 = g_buf2[0][2];
    float* bB0 = g_buf2[1][0]; float* bB1 = g_buf2[1][1]; float* bB2 = g_buf2[1][2];

    // prefetch token features for t=0 (group A: seqs 0-7, group B: seqs 8-15)
    float egvA[4], egvB[4];
#pragma unroll
    for (int k = 0; k < 4; k++) {
        int i = k * 256 + tid, n = i >> 7, d = i & 127;
        egvA[k] = __ldg(&g_Ele[(size_t)__ldg(&text[n * Tt]) * Dn + d]);
        egvB[k] = __ldg(&g_Ele[(size_t)__ldg(&text[(8 + n) * Tt]) * Dn + d]);
    }

    for (int t = 0; t < Tt; t++) {
        // ================= group A =================
        GB_WAIT(0, genA);
        {
            // z-pass: warp w owns batch w (8 warps = 8 batches)
            float4 g = __ldcg((const float4*)(bA0 + w * Dn + lane * 4));
            float4 s4 = *(const float4*)&snS[lane * 4];
            float z = g.x * s4.x + g.y * s4.y + g.z * s4.z + g.w * s4.w;
#pragma unroll
            for (int o = 16; o; o >>= 1) z += __shfl_xor_sync(~0u, z, o);
            if (blk == (t & 127) && lane == 0 && t > 0) __stcg(&g_Zs[0][t][w], z);
            float inv = 1.f / z;
            g.x *= inv; g.y *= inv; g.z *= inv; g.w *= inv;
            *(float4*)&Gs[0][w][lane * 4] = g;
#pragma unroll
            for (int k = 0; k < 4; k++) {
                int i = k * 256 + tid;
                Egs[0][i >> 7][i & 127] = egvA[k];
            }
        }
        __syncthreads();
#pragma unroll
        for (int n = 0; n < NG; n++) {
            float eo = 0.f, mo = 0.f;
#pragma unroll
            for (int j = 0; j < 4; j++) {
                float4 e = *(const float4*)&Egs[0][n][j * 32 + q * 4];
                float4 g = *(const float4*)&Gs[0][n][j * 32 + q * 4];
                eo += a[j*4]*e.x + a[j*4+1]*e.y + a[j*4+2]*e.z + a[j*4+3]*e.w;
                mo += b[j*4]*g.x + b[j*4+1]*g.y + b[j*4+2]*g.z + b[j*4+3]*g.w;
            }
#pragma unroll
            for (int o = 4; o; o >>= 1) {
                eo += __shfl_xor_sync(~0u, eo, o);
                mo += __shfl_xor_sync(~0u, mo, o);
            }
            if (q == 0) Ash[0][n][cl] = eo * mo;
        }
        __syncthreads();
#pragma unroll
        for (int k = 0; k < 4; k++) {
            int n = k * 2 + half;
            float acc = 0.f;
            const float* arow = Ash[0][n];
#pragma unroll
            for (int c = 0; c < 32; c++) acc += arow[c] * xn[c];
            atomicAdd(&bA1[n * Dn + dd], acc);
        }
        if (tid < 8) __stcg(&bA2[blk * 8 + tid], 0.f);
        GB_ARRIVE(0);
        // prefetch next A tokens (overlaps group-B wait + work)
        if (t + 1 < Tt) {
#pragma unroll
            for (int k = 0; k < 4; k++) {
                int i = k * 256 + tid, n = i >> 7, d = i & 127;
                egvA[k] = __ldg(&g_Ele[(size_t)__ldg(&text[n * Tt + t + 1]) * Dn + d]);
            }
        }

        // ================= group B =================
        GB_WAIT(1, genB);
        {
            float4 g = __ldcg((const float4*)(bB0 + w * Dn + lane * 4));
            float4 s4 = *(const float4*)&snS[lane * 4];
            float z = g.x * s4.x + g.y * s4.y + g.z * s4.z + g.w * s4.w;
#pragma unroll
            for (int o = 16; o; o >>= 1) z += __shfl_xor_sync(~0u, z, o);
            if (blk == (t & 127) && lane == 0 && t > 0) __stcg(&g_Zs[1][t][w], z);
            float inv = 1.f / z;
            g.x *= inv; g.y *= inv; g.z *= inv; g.w *= inv;
            *(float4*)&Gs[1][w][lane * 4] = g;
#pragma unroll
            for (int k = 0; k < 4; k++) {
                int i = k * 256 + tid;
                Egs[1][i >> 7][i & 127] = egvB[k];
            }
        }
        __syncthreads();
#pragma unroll
        for (int n = 0; n < NG; n++) {
            float eo = 0.f, mo = 0.f;
#pragma unroll
            for (int j = 0; j < 4; j++) {
                float4 e = *(const float4*)&Egs[1][n][j * 32 + q * 4];
                float4 g = *(const float4*)&Gs[1][n][j * 32 + q * 4];
                eo += a[j*4]*e.x + a[j*4+1]*e.y + a[j*4+2]*e.z + a[j*4+3]*e.w;
                mo += b[j*4]*g.x + b[j*4+1]*g.y + b[j*4+2]*g.z + b[j*4+3]*g.w;
            }
#pragma unroll
            for (int o = 4; o; o >>= 1) {
                eo += __shfl_xor_sync(~0u, eo, o);
                mo += __shfl_xor_sync(~0u, mo, o);
            }
            if (q == 0) Ash[1][n][cl] = eo * mo;
        }
        __syncthreads();
#pragma unroll
        for (int k = 0; k < 4; k++) {
            int n = k * 2 + half;
            float acc = 0.f;
            const float* arow = Ash[1][n];
#pragma unroll
            for (int c = 0; c < 32; c++) acc += arow[c] * xn[c];
            atomicAdd(&bB1[n * Dn + dd], acc);
        }
        if (tid < 8) __stcg(&bB2[blk * 8 + tid], 0.f);
        GB_ARRIVE(1);
        if (t + 1 < Tt) {
#pragma unroll
            for (int k = 0; k < 4; k++) {
                int i = k * 256 + tid, n = i >> 7, d = i & 127;
                egvB[k] = __ldg(&g_Ele[(size_t)__ldg(&text[(8 + n) * Tt + t + 1]) * Dn + d]);
            }
        }

        // rotate both buffer sets
        float* tp;
        tp = bA0; bA0 = bA1; bA1 = bA2; bA2 = tp;
        tp = bB0; bB0 = bB1; bB1 = bB2; bB2 = tp;
    }

    // ---- finalize: block 0 computes final z's and sums all 4096 logs ----
    if (blk == 0) {
        GB_WAIT(0, genA);
        GB_WAIT(1, genB);
        {
            float4 s4 = *(const float4*)&snS[lane * 4];
            float4 ga = __ldcg((const float4*)(bA0 + w * Dn + lane * 4));
            float4 gb = __ldcg((const float4*)(bB0 + w * Dn + lane * 4));
            float za = ga.x*s4.x + ga.y*s4.y + ga.z*s4.z + ga.w*s4.w;
            float zb = gb.x*s4.x + gb.y*s4.y + gb.z*s4.z + gb.w*s4.w;
#pragma unroll
            for (int o = 16; o; o >>= 1) {
                za += __shfl_xor_sync(~0u, za, o);
                zb += __shfl_xor_sync(~0u, zb, o);
            }
            if (lane == 0) { __stcg(&g_Zs[0][0][w], za); __stcg(&g_Zs[1][0][w], zb); }
        }
        __syncthreads();
        __shared__ float red[8];
        float s = 0.f;
        const float* zp = (const float*)g_Zs;
        for (int i = tid; i < 2 * Tt * NG; i += 256) s += logf(__ldcg(&zp[i]));
#pragma unroll
        for (int o = 16; o; o >>= 1) s += __shfl_xor_sync(~0u, s, o);
        if (lane == 0) red[w] = s;
        __syncthreads();
        if (tid == 0) {
            float tot = 0.f;
#pragma unroll
            for (int i = 0; i < 8; i++) tot += red[i];
            out[0] = tot;
        }
    }
}

extern "C" void kernel_launch(void* const* d_in, const int* in_sizes, int n_in,
                              void* d_out, int out_size) {
    (void)n_in; (void)out_size;
    const float *se, *sw0, *sb0, *sw1, *sb1, *sw2, *sb2, *sw3, *sb3, *sw4, *sb4;
    const float *state_emb, *next_state_emb, *pre_emb;
    const float *tw1, *tb1, *tw2, *tb2, *tw3, *tb3, *tw4, *tb4, *term_emb, *proj;
    const int* text;
    if (in_sizes[0] == Hn) {
        se  = (const float*)d_in[0];
        sw0 = (const float*)d_in[1];  sb0 = (const float*)d_in[2];
        sw1 = (const float*)d_in[3];  sb1 = (const float*)d_in[4];
        sw2 = (const float*)d_in[5];  sb2 = (const float*)d_in[6];
        sw3 = (const float*)d_in[7];  sb3 = (const float*)d_in[8];
        sw4 = (const float*)d_in[9];  sb4 = (const float*)d_in[10];
        state_emb = (const float*)d_in[11];
        next_state_emb = (const float*)d_in[12];
        pre_emb = (const float*)d_in[13];
        tw1 = (const float*)d_in[14]; tb1 = (const float*)d_in[15];
        tw2 = (const float*)d_in[16]; tb2 = (const float*)d_in[17];
        tw3 = (const float*)d_in[18]; tb3 = (const float*)d_in[19];
        tw4 = (const float*)d_in[20]; tb4 = (const float*)d_in[21];
        term_emb = (const float*)d_in[22];
        proj = (const float*)d_in[23];
        text = (const int*)d_in[24];
    } else {
        text = (const int*)d_in[0];
        se  = (const float*)d_in[2];
        sw0 = (const float*)d_in[3];  sb0 = (const float*)d_in[4];
        sw1 = (const float*)d_in[5];  sb1 = (const float*)d_in[6];
        sw2 = (const float*)d_in[7];  sb2 = (const float*)d_in[8];
        sw3 = (const float*)d_in[9];  sb3 = (const float*)d_in[10];
        sw4 = (const float*)d_in[11]; sb4 = (const float*)d_in[12];
        tw1 = (const float*)d_in[13]; tb1 = (const float*)d_in[14];
        tw2 = (const float*)d_in[15]; tb2 = (const float*)d_in[16];
        tw3 = (const float*)d_in[17]; tb3 = (const float*)d_in[18];
        tw4 = (const float*)d_in[19]; tb4 = (const float*)d_in[20];
        state_emb = (const float*)d_in[21];
        next_state_emb = (const float*)d_in[22];
        pre_emb = (const float*)d_in[23];
        term_emb = (const float*)d_in[24];
        proj = (const float*)d_in[25];
    }

    float *pXn, *pT1, *pF1, *pT2, *pFt, *pEyn, *pExn, *pExt, *pEle, *pSn, *pSe;
    cudaGetSymbolAddress((void**)&pXn, g_Xn);
    cudaGetSymbolAddress((void**)&pT1, g_t1);
    cudaGetSymbolAddress((void**)&pF1, g_f1);
    cudaGetSymbolAddress((void**)&pT2, g_t2);
    cudaGetSymbolAddress((void**)&pFt, g_ft);
    cudaGetSymbolAddress((void**)&pEyn, g_Eyn);
    cudaGetSymbolAddress((void**)&pExn, g_Exn);
    cudaGetSymbolAddress((void**)&pExt, g_Ext);
    cudaGetSymbolAddress((void**)&pEle, g_Ele);
    cudaGetSymbolAddress((void**)&pSn, g_Sn);
    cudaGetSymbolAddress((void**)&pSe, g_Se);

    kzero<<<1, 128>>>();

    // terminal MLP: two ResLayers on preterminal_emb
    kgemm<<<dim3(Cn / 64, 4), 256>>>(pre_emb, tw1, tb1, nullptr, pT1, Cn, Hn, Hn, 1);
    kgemm<<<dim3(Cn / 64, 4), 256>>>(pT1, tw2, tb2, pre_emb, pF1, Cn, Hn, Hn, 2);
    kgemm<<<dim3(Cn / 64, 4), 256>>>(pF1, tw3, tb3, nullptr, pT2, Cn, Hn, Hn, 1);
    kgemm<<<dim3(Cn / 64, 4), 256>>>(pT2, tw4, tb4, pF1, pFt, Cn, Hn, Hn, 2);

    // features
    krownorm<<<Cn, 256>>>(next_state_emb, pXn);
    kgemm<<<dim3(Cn / 64, 2), 256>>>(pXn, proj, nullptr, nullptr, pEyn, Cn, Dn, Hn, 3);
    kcolsum<<<256, 128>>>(pEyn, Cn, pSn);

    krownorm<<<Cn, 256>>>(state_emb, pXn);
    kgemm<<<dim3(Cn / 64, 2), 256>>>(pXn, proj, nullptr, nullptr, pExn, Cn, Dn, Hn, 3);
    krowdiv<<<Cn, 128>>>(pExn, pSn);   // ExnN: rows sum to 1 against Sn

    krownorm<<<Cn, 256>>>(pFt, pXn);
    kgemm<<<dim3(Cn / 64, 2), 256>>>(pXn, proj, nullptr, nullptr, pExt, Cn, Dn, Hn, 3);

    krownorm<<<Vn, 256>>>(term_emb, pXn);
    kgemm<<<dim3(Vn / 64, 2), 256>>>(pXn, proj, nullptr, nullptr, pEle, Vn, Dn, Hn, 3);
    kcolsum<<<256, 128>>>(pEle, Vn, pSe);
    krowdiv<<<Cn, 128>>>(pExt, pSe);   // ExtN

    kstartmlp<<<1, 256>>>(se, sw0, sb0, sw1, sb1, sw2, sb2, sw3, sb3, sw4, sb4, proj);

    // the whole 256-step recursion in ONE launch, 2 interleaved groups
    krec<<<NBLK, 256>>>(text, (float*)d_out);
}

// round 14
// speedup vs baseline: 1.7233x; 1.7233x over previous
#include <cuda_runtime.h>
#include <math.h>

#define Cn 4096
#define Vn 32000
#define Hn 256
#define Dn 128
#define Nb 16
#define Tt 256
#define NBLK 128

// ---------------- device scratch (static) ----------------
__device__ float g_Xn[Vn * Hn];        // normalized-row staging (max V rows)
__device__ float g_t1[Cn * Hn];
__device__ float g_f1[Cn * Hn];
__device__ float g_t2[Cn * Hn];
__device__ float g_ft[Cn * Hn];
__device__ float g_Eyn[Cn * Dn];       // features of next_state_emb
__device__ float g_Exn[Cn * Dn];       // features of state_emb (row-normalized: ExnN·Sn = 1)
__device__ float g_Ext[Cn * Dn];       // features of terminal-MLP out (row-normalized by Se)
__device__ float g_Ele[Vn * Dn];       // features of terminal_emb
__device__ float g_Sn[Dn];
__device__ float g_Se[Dn];
__device__ float g_Exs[Dn];
__device__ float g_buf[3][Nb][Dn];     // rotating G state buffers
__device__ unsigned g_flag[NBLK * 8];  // per-block barrier flags (32B stride, no atomics)

// ---------------- zero / reset ----------------
__global__ __launch_bounds__(256) void kzero() {
    int i = threadIdx.x;
    if (i < Dn) { g_Sn[i] = 0.f; g_Se[i] = 0.f; }
    for (int j = i; j < NBLK * 8; j += 256) g_flag[j] = 0u;
}

// ------------- generic tiled GEMM: Out = epi(A[M,K]@W[K,N]) -------------
// mode 1: relu(+bias); 2: relu(+bias)+R; 3: exp(x-0.5)
__global__ __launch_bounds__(256) void kgemm(const float* __restrict__ A,
                                             const float* __restrict__ W,
                                             const float* __restrict__ bias,
                                             const float* __restrict__ R,
                                             float* __restrict__ Out,
                                             int M, int N, int K, int mode) {
    __shared__ float As[16][68];
    __shared__ float Ws[16][68];
    int tid = threadIdx.x;
    int m0 = blockIdx.x * 64, n0 = blockIdx.y * 64;
    int ar = tid >> 2, ak = (tid & 3) * 4;
    int wk = tid >> 4, wn = (tid & 15) * 4;
    int ty = tid >> 4, tx = tid & 15;
    float acc[4][4] = {};
    for (int kt = 0; kt < K; kt += 16) {
        float4 av = *(const float4*)(A + (size_t)(m0 + ar) * K + kt + ak);
        As[ak + 0][ar] = av.x; As[ak + 1][ar] = av.y;
        As[ak + 2][ar] = av.z; As[ak + 3][ar] = av.w;
        *(float4*)&Ws[wk][wn] = *(const float4*)(W + (size_t)(kt + wk) * N + n0 + wn);
        __syncthreads();
#pragma unroll
        for (int k = 0; k < 16; k++) {
            float a[4], b[4];
            *(float4*)a = *(const float4*)&As[k][ty * 4];
            *(float4*)b = *(const float4*)&Ws[k][tx * 4];
#pragma unroll
            for (int i = 0; i < 4; i++)
#pragma unroll
                for (int j = 0; j < 4; j++) acc[i][j] += a[i] * b[j];
        }
        __syncthreads();
    }
#pragma unroll
    for (int i = 0; i < 4; i++) {
        int m = m0 + ty * 4 + i;
#pragma unroll
        for (int j = 0; j < 4; j++) {
            int n = n0 + tx * 4 + j;
            float v = acc[i][j];
            if (mode == 1 || mode == 2) v = fmaxf(v + bias[n], 0.f);
            if (mode == 2) v += R[(size_t)m * N + n];
            if (mode == 3) v = expf(v - 0.5f);
            Out[(size_t)m * N + n] = v;
        }
    }
}

// ------------- row l2-normalize -------------
__global__ __launch_bounds__(256) void krownorm(const float* __restrict__ X,
                                                float* __restrict__ Xn) {
    int r = blockIdx.x, tid = threadIdx.x;
    __shared__ float red[8];
    float v = X[(size_t)r * Hn + tid];
    float ss = v * v;
#pragma unroll
    for (int o = 16; o; o >>= 1) ss += __shfl_xor_sync(~0u, ss, o);
    if ((tid & 31) == 0) red[tid >> 5] = ss;
    __syncthreads();
    float tot = 0.f;
#pragma unroll
    for (int i = 0; i < 8; i++) tot += red[i];
    Xn[(size_t)r * Hn + tid] = v * rsqrtf(tot);
}

// ------------- column sums -------------
__global__ __launch_bounds__(128) void kcolsum(const float* __restrict__ E, int rows,
                                               float* __restrict__ S) {
    int d = threadIdx.x;
    float acc = 0.f;
    for (int r = blockIdx.x; r < rows; r += gridDim.x) acc += E[(size_t)r * Dn + d];
    atomicAdd(&S[d], acc);
}

// ------------- row normalize: E[r,:] /= (E[r,:]·S) -------------
__global__ __launch_bounds__(128) void krowdiv(float* __restrict__ E,
                                               const float* __restrict__ S) {
    int r = blockIdx.x, tid = threadIdx.x;
    __shared__ float red[4];
    float v = E[(size_t)r * Dn + tid];
    float p = v * S[tid];
#pragma unroll
    for (int o = 16; o; o >>= 1) p += __shfl_xor_sync(~0u, p, o);
    if ((tid & 31) == 0) red[tid >> 5] = p;
    __syncthreads();
    float u = red[0] + red[1] + red[2] + red[3];
    E[(size_t)r * Dn + tid] = v / u;
}

// ------------- start MLP + features of the single start vector -------------
__global__ __launch_bounds__(256) void kstartmlp(
    const float* se, const float* w0, const float* b0,
    const float* w1, const float* b1, const float* w2, const float* b2,
    const float* w3, const float* b3, const float* w4, const float* b4,
    const float* proj) {
    __shared__ float xs[256], Ab[256], Bb[256], Cb[256];
    __shared__ float red[8], sinv;
    int tid = threadIdx.x;
    xs[tid] = se[tid];
    __syncthreads();
    float acc = 0.f;
    for (int i = 0; i < 256; i++) acc += xs[i] * w0[i * 256 + tid];
    Ab[tid] = acc + b0[tid];
    __syncthreads();
    acc = 0.f;
    for (int i = 0; i < 256; i++) acc += Ab[i] * w1[i * 256 + tid];
    Bb[tid] = fmaxf(acc + b1[tid], 0.f);
    __syncthreads();
    acc = 0.f;
    for (int i = 0; i < 256; i++) acc += Bb[i] * w2[i * 256 + tid];
    Cb[tid] = fmaxf(acc + b2[tid], 0.f) + Ab[tid];
    __syncthreads();
    acc = 0.f;
    for (int i = 0; i < 256; i++) acc += Cb[i] * w3[i * 256 + tid];
    __syncthreads();
    Bb[tid] = fmaxf(acc + b3[tid], 0.f);
    __syncthreads();
    acc = 0.f;
    for (int i = 0; i < 256; i++) acc += Bb[i] * w4[i * 256 + tid];
    Ab[tid] = fmaxf(acc + b4[tid], 0.f) + Cb[tid];
    __syncthreads();
    float ss = Ab[tid] * Ab[tid];
#pragma unroll
    for (int o = 16; o; o >>= 1) ss += __shfl_xor_sync(~0u, ss, o);
    if ((tid & 31) == 0) red[tid >> 5] = ss;
    __syncthreads();
    if (tid == 0) {
        float t = 0.f;
        for (int i = 0; i < 8; i++) t += red[i];
        sinv = rsqrtf(t);
    }
    __syncthreads();
    if (tid < 128) {
        float a2 = 0.f;
        for (int i = 0; i < 256; i++) a2 += Ab[i] * proj[i * 128 + tid];
        g_Exs[tid] = expf(a2 * sinv - 0.5f);
    }
}

// =========== persistent recursion kernel: all 256 HMM steps ===========
// Flag-array grid barrier: arrival = plain store to own 32B slot (no atomic
// serialization); wait = 128 threads each poll one flag; monotonic generation.
__global__ __launch_bounds__(256, 1) void krec(const int* __restrict__ text,
                                               float* __restrict__ out) {
    __shared__ float Gs[Nb][Dn];
    __shared__ float Egs[Nb][Dn];
    __shared__ float Ash[Nb][32];
    __shared__ float zsh[Nb];
    __shared__ float snS[Dn];
    int tid = threadIdx.x;
    int blk = blockIdx.x;
    int w = tid >> 5, lane = tid & 31;
    int cl = tid >> 3, q = tid & 7;
    int dd = tid & 127, half = tid >> 7;
    unsigned want = 1;

    // persistent operands: thread owns d-chunks {j*32 + q*4 .. +3} of its state row
    float a[16], b[16], xn[32];
    {
        const float4* ap = (const float4*)(g_Ext + (size_t)(blk * 32 + cl) * Dn + q * 4);
        const float4* bp = (const float4*)(g_Eyn + (size_t)(blk * 32 + cl) * Dn + q * 4);
#pragma unroll
        for (int j = 0; j < 4; j++) {
            *(float4*)&a[j * 4] = ap[j * 8];   // stride 32 floats = 8 float4
            *(float4*)&b[j * 4] = bp[j * 8];
        }
#pragma unroll
        for (int k = 0; k < 32; k++) xn[k] = g_Exn[(size_t)(blk * 32 + k) * Dn + dd];
    }
    if (tid < Dn) snS[tid] = g_Sn[tid];

    // init rotating buffers: buf0 = Exs replicated, buf1 = 0
    if (tid < 16) {
        int ib = blk * 16 + tid;
        __stcg(&((float*)g_buf[0])[ib], g_Exs[ib & 127]);
        __stcg(&((float*)g_buf[1])[ib], 0.f);
    }
    float evAcc = 0.f;

    // ---- barrier (init) ----
    __threadfence();
    __syncthreads();
    if (tid == 0) *(volatile unsigned*)&g_flag[blk * 8] = want;
    if (tid < NBLK) {
        volatile unsigned* fl = &g_flag[tid * 8];
        while (*fl < want) __nanosleep(32);
    }
    __syncthreads();
    want++;

    float* bufp0 = (float*)g_buf[0];
    float* bufp1 = (float*)g_buf[1];
    float* bufp2 = (float*)g_buf[2];

    // prefetch token features for t=0
    float egv[8];
#pragma unroll
    for (int k = 0; k < 8; k++) {
        int i = k * 256 + tid, n = i >> 7, d = i & 127;
        int tk = __ldg(&text[n * Tt + 0]);
        egv[k] = __ldg(&g_Ele[(size_t)tk * Dn + d]);
    }

    for (int t = 0; t < Tt; t++) {
        const float* Gcur = bufp0;
        float* Gnext = bufp1;
        float* Gz = bufp2;

        // z[n] = G[n,:]·Sn ; ghat = G/z  (warp w owns batches w and w+8)
        {
            float4 ga = __ldcg((const float4*)(Gcur + w * Dn + lane * 4));
            float4 gb = __ldcg((const float4*)(Gcur + (w + 8) * Dn + lane * 4));
            float4 s4 = *(const float4*)&snS[lane * 4];
            float za = ga.x * s4.x + ga.y * s4.y + ga.z * s4.z + ga.w * s4.w;
            float zb = gb.x * s4.x + gb.y * s4.y + gb.z * s4.z + gb.w * s4.w;
#pragma unroll
            for (int o = 16; o; o >>= 1) {
                za += __shfl_xor_sync(~0u, za, o);
                zb += __shfl_xor_sync(~0u, zb, o);
            }
            if (lane == 0) { zsh[w] = za; zsh[w + 8] = zb; }
            float ia = 1.f / za, ib2 = 1.f / zb;
            ga.x *= ia; ga.y *= ia; ga.z *= ia; ga.w *= ia;
            gb.x *= ib2; gb.y *= ib2; gb.z *= ib2; gb.w *= ib2;
            *(float4*)&Gs[w][lane * 4] = ga;
            *(float4*)&Gs[w + 8][lane * 4] = gb;
        }
        // stage token features
#pragma unroll
        for (int k = 0; k < 8; k++) ((float*)Egs)[k * 256 + tid] = egv[k];
        __syncthreads();
        if (blk == 0 && tid < 16 && t > 0) evAcc += logf(zsh[tid]);

        // A[n,c] = (ExtN_c·Ele_n) * (ghat_n·Eyn_c)
#pragma unroll
        for (int n = 0; n < Nb; n++) {
            float eo = 0.f, mo = 0.f;
#pragma unroll
            for (int j = 0; j < 4; j++) {
                float4 e = *(const float4*)&Egs[n][j * 32 + q * 4];
                float4 g = *(const float4*)&Gs[n][j * 32 + q * 4];
                eo += a[j*4]*e.x + a[j*4+1]*e.y + a[j*4+2]*e.z + a[j*4+3]*e.w;
                mo += b[j*4]*g.x + b[j*4+1]*g.y + b[j*4+2]*g.z + b[j*4+3]*g.w;
            }
#pragma unroll
            for (int o = 4; o; o >>= 1) {
                eo += __shfl_xor_sync(~0u, eo, o);
                mo += __shfl_xor_sync(~0u, mo, o);
            }
            if (q == 0) Ash[n][cl] = eo * mo;
        }
        __syncthreads();

        // G'[n,d] += A[n, block slice] @ ExnN[block slice, d]
#pragma unroll
        for (int k = 0; k < 8; k++) {
            int n = 2 * k + half;
            float acc = 0.f;
            const float* arow = Ash[n];
#pragma unroll
            for (int c2 = 0; c2 < 32; c2++) acc += arow[c2] * xn[c2];
            atomicAdd(&Gnext[n * Dn + dd], acc);
        }
        // zero the buffer that becomes Gnext at t+1
        if (tid < 16) __stcg(&Gz[blk * 16 + tid], 0.f);

        // ---- barrier: arrive, prefetch under the window, poll ----
        __threadfence();
        __syncthreads();
        if (tid == 0) *(volatile unsigned*)&g_flag[blk * 8] = want;
        if (t + 1 < Tt) {
#pragma unroll
            for (int k = 0; k < 8; k++) {
                int i = k * 256 + tid, n = i >> 7, d = i & 127;
                int tk = __ldg(&text[n * Tt + t + 1]);
                egv[k] = __ldg(&g_Ele[(size_t)tk * Dn + d]);
            }
        }
        if (tid < NBLK) {
            volatile unsigned* fl = &g_flag[tid * 8];
            while (*fl < want) __nanosleep(32);
        }
        __syncthreads();
        want++;

        float* tmp = bufp0; bufp0 = bufp1; bufp1 = bufp2; bufp2 = tmp;
    }

    // finalize: block 0 adds log Z of the last step and reduces evidence
    if (blk == 0) {
        const float* Gf = bufp0;
        float4 ga = __ldcg((const float4*)(Gf + w * Dn + lane * 4));
        float4 gb = __ldcg((const float4*)(Gf + (w + 8) * Dn + lane * 4));
        float4 s4 = *(const float4*)&snS[lane * 4];
        float za = ga.x * s4.x + ga.y * s4.y + ga.z * s4.z + ga.w * s4.w;
        float zb = gb.x * s4.x + gb.y * s4.y + gb.z * s4.z + gb.w * s4.w;
#pragma unroll
        for (int o = 16; o; o >>= 1) {
            za += __shfl_xor_sync(~0u, za, o);
            zb += __shfl_xor_sync(~0u, zb, o);
        }
        if (lane == 0) { zsh[w] = za; zsh[w + 8] = zb; }
        __syncthreads();
        if (tid < 16) evAcc += logf(zsh[tid]);
        if (w == 0) {
#pragma unroll
            for (int o = 8; o; o >>= 1) evAcc += __shfl_xor_sync(~0u, evAcc, o);
            if (tid == 0) out[0] = evAcc;
        }
    }
}

extern "C" void kernel_launch(void* const* d_in, const int* in_sizes, int n_in,
                              void* d_out, int out_size) {
    (void)n_in; (void)out_size;
    const float *se, *sw0, *sb0, *sw1, *sb1, *sw2, *sb2, *sw3, *sb3, *sw4, *sb4;
    const float *state_emb, *next_state_emb, *pre_emb;
    const float *tw1, *tb1, *tw2, *tb2, *tw3, *tb3, *tw4, *tb4, *term_emb, *proj;
    const int* text;
    if (in_sizes[0] == Hn) {
        se  = (const float*)d_in[0];
        sw0 = (const float*)d_in[1];  sb0 = (const float*)d_in[2];
        sw1 = (const float*)d_in[3];  sb1 = (const float*)d_in[4];
        sw2 = (const float*)d_in[5];  sb2 = (const float*)d_in[6];
        sw3 = (const float*)d_in[7];  sb3 = (const float*)d_in[8];
        sw4 = (const float*)d_in[9];  sb4 = (const float*)d_in[10];
        state_emb = (const float*)d_in[11];
        next_state_emb = (const float*)d_in[12];
        pre_emb = (const float*)d_in[13];
        tw1 = (const float*)d_in[14]; tb1 = (const float*)d_in[15];
        tw2 = (const float*)d_in[16]; tb2 = (const float*)d_in[17];
        tw3 = (const float*)d_in[18]; tb3 = (const float*)d_in[19];
        tw4 = (const float*)d_in[20]; tb4 = (const float*)d_in[21];
        term_emb = (const float*)d_in[22];
        proj = (const float*)d_in[23];
        text = (const int*)d_in[24];
    } else {
        text = (const int*)d_in[0];
        se  = (const float*)d_in[2];
        sw0 = (const float*)d_in[3];  sb0 = (const float*)d_in[4];
        sw1 = (const float*)d_in[5];  sb1 = (const float*)d_in[6];
        sw2 = (const float*)d_in[7];  sb2 = (const float*)d_in[8];
        sw3 = (const float*)d_in[9];  sb3 = (const float*)d_in[10];
        sw4 = (const float*)d_in[11]; sb4 = (const float*)d_in[12];
        tw1 = (const float*)d_in[13]; tb1 = (const float*)d_in[14];
        tw2 = (const float*)d_in[15]; tb2 = (const float*)d_in[16];
        tw3 = (const float*)d_in[17]; tb3 = (const float*)d_in[18];
        tw4 = (const float*)d_in[19]; tb4 = (const float*)d_in[20];
        state_emb = (const float*)d_in[21];
        next_state_emb = (const float*)d_in[22];
        pre_emb = (const float*)d_in[23];
        term_emb = (const float*)d_in[24];
        proj = (const float*)d_in[25];
    }

    float *pXn, *pT1, *pF1, *pT2, *pFt, *pEyn, *pExn, *pExt, *pEle, *pSn, *pSe;
    cudaGetSymbolAddress((void**)&pXn, g_Xn);
    cudaGetSymbolAddress((void**)&pT1, g_t1);
    cudaGetSymbolAddress((void**)&pF1, g_f1);
    cudaGetSymbolAddress((void**)&pT2, g_t2);
    cudaGetSymbolAddress((void**)&pFt, g_ft);
    cudaGetSymbolAddress((void**)&pEyn, g_Eyn);
    cudaGetSymbolAddress((void**)&pExn, g_Exn);
    cudaGetSymbolAddress((void**)&pExt, g_Ext);
    cudaGetSymbolAddress((void**)&pEle, g_Ele);
    cudaGetSymbolAddress((void**)&pSn, g_Sn);
    cudaGetSymbolAddress((void**)&pSe, g_Se);

    kzero<<<1, 256>>>();

    // terminal MLP: two ResLayers on preterminal_emb
    kgemm<<<dim3(Cn / 64, 4), 256>>>(pre_emb, tw1, tb1, nullptr, pT1, Cn, Hn, Hn, 1);
    kgemm<<<dim3(Cn / 64, 4), 256>>>(pT1, tw2, tb2, pre_emb, pF1, Cn, Hn, Hn, 2);
    kgemm<<<dim3(Cn / 64, 4), 256>>>(pF1, tw3, tb3, nullptr, pT2, Cn, Hn, Hn, 1);
    kgemm<<<dim3(Cn / 64, 4), 256>>>(pT2, tw4, tb4, pF1, pFt, Cn, Hn, Hn, 2);

    // features
    krownorm<<<Cn, 256>>>(next_state_emb, pXn);
    kgemm<<<dim3(Cn / 64, 2), 256>>>(pXn, proj, nullptr, nullptr, pEyn, Cn, Dn, Hn, 3);
    kcolsum<<<256, 128>>>(pEyn, Cn, pSn);

    krownorm<<<Cn, 256>>>(state_emb, pXn);
    kgemm<<<dim3(Cn / 64, 2), 256>>>(pXn, proj, nullptr, nullptr, pExn, Cn, Dn, Hn, 3);
    krowdiv<<<Cn, 128>>>(pExn, pSn);   // ExnN: rows sum to 1 against Sn

    krownorm<<<Cn, 256>>>(pFt, pXn);
    kgemm<<<dim3(Cn / 64, 2), 256>>>(pXn, proj, nullptr, nullptr, pExt, Cn, Dn, Hn, 3);

    krownorm<<<Vn, 256>>>(term_emb, pXn);
    kgemm<<<dim3(Vn / 64, 2), 256>>>(pXn, proj, nullptr, nullptr, pEle, Vn, Dn, Hn, 3);
    kcolsum<<<256, 128>>>(pEle, Vn, pSe);
    krowdiv<<<Cn, 128>>>(pExt, pSe);   // ExtN

    kstartmlp<<<1, 256>>>(se, sw0, sb0, sw1, sb1, sw2, sb2, sw3, sb3, sw4, sb4, proj);

    // the whole 256-step recursion in ONE launch
    krec<<<NBLK, 256>>>(text, (float*)d_out);
}